// round 13
// baseline (speedup 1.0000x reference)
#include <cuda_runtime.h>
#include <math.h>
#include <stdint.h>

#define N 512
#define C 157
#define M 20
#define NC (N*C)
#define CC (C*C)                               /* 24649 floats per aa tile */
#define SIGMA2_INV (1.0f/(2.0f*300.0f*300.0f))
#define EPSV 1e-7f
#define INV_DECAY (1.0f/0.9f)
#define LOG2_INV_DECAY 0.15200309344504997f    /* log2(1/0.9) */
#define RPAD 33                                 /* rowpart pitch (conflict-free) */
#define NW 12                                   /* warps per CTA */
#define NT (NW*32)                              /* 384 threads */

#define CHF 3072                                /* floats per chunk */
#define CHB (CHF*4)                             /* 12288 bytes */
#define NCH 9                                   /* 8 full + 1 tail */
#define LASTB 304                               /* tail chunk bytes (76 floats) */
#define LASTF 76

/* dynamic smem layout (float indices) */
#define S_BUF0   0
#define S_BUF1   CHF
#define S_ROWP   (2*CHF)                        /* C*RPAD = 5181 */
#define S_COLP   (S_ROWP + 5184)                /* NW*160 = 1920 */
#define S_MSG    (S_COLP + 1920)                /* 157 */
#define S_FMSG   (S_MSG + 160)                  /* 157 */
#define S_WP     (S_FMSG + 160)                 /* 20 */
#define S_WF     (S_WP + 20)                    /* 20 */
#define S_WSUM   (S_WF + 20)                    /* 12 */
#define S_DEN    (S_WSUM + 12)                  /* 2 */
#define S_LAST   (S_DEN + 2)                    /* 1 */
#define S_MBAR   (S_DEN + 4)                    /* 4 floats = two u64 mbars (8B aligned) */
#define SMEM_FLOATS (S_MBAR + 4)
#define SMEM_BYTES  (SMEM_FLOATS*4 + 64)

__device__ float g_partial[N];
__device__ unsigned int g_count = 0;

__device__ __forceinline__ uint32_t s2u(const void* p) {
    return (uint32_t)__cvta_generic_to_shared(p);
}
__device__ __forceinline__ void mbar_init(uint32_t mbar, uint32_t cnt) {
    asm volatile("mbarrier.init.shared.b64 [%0], %1;" :: "r"(mbar), "r"(cnt) : "memory");
}
__device__ __forceinline__ void mbar_expect_tx(uint32_t mbar, uint32_t bytes) {
    asm volatile("mbarrier.arrive.expect_tx.shared.b64 _, [%0], %1;"
                 :: "r"(mbar), "r"(bytes) : "memory");
}
__device__ __forceinline__ void bulk_g2s(uint32_t dst, const void* src,
                                         uint32_t bytes, uint32_t mbar) {
    asm volatile("cp.async.bulk.shared::cta.global.mbarrier::complete_tx::bytes "
                 "[%0], [%1], %2, [%3];"
                 :: "r"(dst), "l"(src), "r"(bytes), "r"(mbar) : "memory");
}
__device__ __forceinline__ void mbar_wait(uint32_t mbar, uint32_t parity) {
    asm volatile(
        "{\n\t.reg .pred P;\n\t"
        "WAITLOOP_%=:\n\t"
        "mbarrier.try_wait.parity.acquire.cta.shared::cta.b64 P, [%0], %1, 0x989680;\n\t"
        "@!P bra WAITLOOP_%=;\n\t"
        "}" :: "r"(mbar), "r"(parity) : "memory");
}

__global__ __launch_bounds__(NT, 4) void fused_kernel(
    const float* __restrict__ a, const float* __restrict__ aa,
    const float* __restrict__ target, const float* __restrict__ bank_values,
    const int* __restrict__ bank_times, const int* __restrict__ bank_mask,
    const int* __restrict__ ids, const int* __restrict__ times,
    float* __restrict__ out, int out_size)
{
    extern __shared__ float sm[];
    float* rowpart = sm + S_ROWP;
    float* colp    = sm + S_COLP;
    float* msg_s   = sm + S_MSG;
    float* fmsg_s  = sm + S_FMSG;
    float* wpast   = sm + S_WP;
    float* wfut    = sm + S_WF;
    float* wsum    = sm + S_WSUM;

    const int n = blockIdx.x;
    const int t = threadIdx.x;
    const int w = t >> 5;
    const int l = t & 31;
    const int id = ids[n];

    const int s_bytes = (4*n) & 15;             /* tile base misalignment */
    const int s4f = s_bytes >> 2;               /* pad floats = n&3 */
    const char* src = (const char*)(aa + (size_t)n * CC) - s_bytes;  /* 16B aligned */
    const uint32_t mb0 = s2u(sm + S_MBAR);
    const uint32_t mb1 = mb0 + 8;
    const uint32_t buf0 = s2u(sm + S_BUF0);
    const uint32_t buf1 = s2u(sm + S_BUF1);

    /* ---- thread 0: init mbars + launch first two chunks IMMEDIATELY ---- */
    if (t == 0) {
        mbar_init(mb0, 1);
        mbar_init(mb1, 1);
        asm volatile("fence.proxy.async.shared::cta;" ::: "memory");
        mbar_expect_tx(mb0, CHB);
        bulk_g2s(buf0, src, CHB, mb0);
        mbar_expect_tx(mb1, CHB);
        bulk_g2s(buf1, src + CHB, CHB, mb1);
    }

    /* ---- zero rowpart (accumulated across chunks) ---- */
    for (int e = t; e < C*RPAD; e += NT) rowpart[e] = 0.f;

    /* ---- prefetch bank row + epilogue operands into registers ---- */
    float v[M];
    float av = 0.f, tg = 0.f;
    if (t < C) {
        const float* vals = bank_values + (size_t)id * (M*C);
        #pragma unroll
        for (int m = 0; m < M; m++) v[m] = vals[m*C + t];
        av = a[n*C + t];
        tg = target[n*C + t];
    }

    /* ---- temporal weights: warp 0, ballot-rank ---- */
    if (t < 32) {
        const bool vd = l < M;
        int tsi = 0, mk = 0;
        if (vd) { tsi = bank_times[id*M + l]; mk = bank_mask[id*M + l]; }
        const float t0 = (float)times[n];
        float ts = (float)tsi;
        float d = ts - t0;
        float kern = __expf(-d*d*SIGMA2_INV);
        bool condp = vd && mk && (ts < t0);
        bool condf = vd && mk && (ts > t0);
        unsigned bp = __ballot_sync(0xFFFFFFFFu, condp);
        unsigned bf = __ballot_sync(0xFFFFFFFFu, condf);
        unsigned below = (1u << l) - 1u;
        float dwp = condp ? exp2f(LOG2_INV_DECAY * (float)__popc(bp & below)) : 0.f;
        float dwf = condf ? exp2f(LOG2_INV_DECAY * (float)__popc(bf & below)) : 0.f;
        if (vd) { wpast[l] = dwp * kern; wfut[l] = dwf * kern; }
        if (l == 0) {
            float cp_ = (float)__popc(bp), cf_ = (float)__popc(bf);
            sm[S_DEN+0] = (exp2f(LOG2_INV_DECAY * cp_) - 1.f) / (INV_DECAY - 1.f);
            sm[S_DEN+1] = (exp2f(LOG2_INV_DECAY * cf_) - 1.f) / (INV_DECAY - 1.f);
        }
    }
    __syncthreads();

    /* ---- msg/fmsg (overlapped with TMA fetch of chunks 0/1) ---- */
    if (t < C) {
        float nump = 0.f, numf = 0.f;
        #pragma unroll
        for (int m = 0; m < M; m++) {
            nump = fmaf(wpast[m], v[m], nump);
            numf = fmaf(wfut[m],  v[m], numf);
        }
        float denp = sm[S_DEN+0], denf = sm[S_DEN+1];
        msg_s[t]  = (denp > 0.f) ? nump / fmaxf(denp, EPSV) : 0.f;
        fmsg_s[t] = (denf > 0.f) ? numf / fmaxf(denf, EPSV) : 0.f;
    }
    __syncthreads();

    /* ---- pipelined consumption of aa chunks ---- */
    const bool q4ok = (l + 128) < C;
    float fm0 = fmsg_s[l];
    float fm1 = fmsg_s[l + 32];
    float fm2 = fmsg_s[l + 64];
    float fm3 = fmsg_s[l + 96];
    float fm4 = q4ok ? fmsg_s[l + 128] : 0.f;
    float c0 = 0.f, c1 = 0.f, c2 = 0.f, c3 = 0.f, c4 = 0.f;

    for (int k = 0; k < NCH; k++) {
        mbar_wait((k & 1) ? mb1 : mb0, (k >> 1) & 1);

        const float* ch = sm + ((k & 1) ? S_BUF1 : S_BUF0);
        int fs = k*CHF - s4f;
        int fe = fs + ((k < NCH-1) ? CHF : LASTF);
        if (fs < 0) fs = 0;
        if (fe > CC) fe = CC;
        int i0 = fs / C;
        int iend = (fe + C - 1) / C;
        int istart = i0 + (((w - (i0 % NW)) + NW) % NW);
        const int cbase = s4f - k*CHF;

        for (int i = istart; i < iend; i += NW) {
            int rb = i * C;
            int ja = fs - rb; if (ja < 0) ja = 0;
            int jb = fe - rb; if (jb > C) jb = C;
            const float* rp = ch + cbase + rb;
            float mi = msg_s[i];
            float rs = 0.f;
            {
                int j = l;
                if (j >= ja && j < jb) { float x = rp[j]; c0 = fmaf(x, mi, c0); rs = fmaf(x, fm0, rs); }
            }
            {
                int j = l + 32;
                if (j >= ja && j < jb) { float x = rp[j]; c1 = fmaf(x, mi, c1); rs = fmaf(x, fm1, rs); }
            }
            {
                int j = l + 64;
                if (j >= ja && j < jb) { float x = rp[j]; c2 = fmaf(x, mi, c2); rs = fmaf(x, fm2, rs); }
            }
            {
                int j = l + 96;
                if (j >= ja && j < jb) { float x = rp[j]; c3 = fmaf(x, mi, c3); rs = fmaf(x, fm3, rs); }
            }
            {
                int j = l + 128;
                if (j >= ja && j < jb) { float x = rp[j]; c4 = fmaf(x, mi, c4); rs = fmaf(x, fm4, rs); }
            }
            rowpart[i*RPAD + l] += rs;
        }
        __syncthreads();     /* slot (k&1) fully consumed by all warps */

        if (t == 0 && (k + 2) < NCH) {
            uint32_t bytes = ((k + 2) < NCH-1) ? CHB : LASTB;
            uint32_t mb = (k & 1) ? mb1 : mb0;
            mbar_expect_tx(mb, bytes);
            bulk_g2s((k & 1) ? buf1 : buf0, src + (size_t)(k + 2)*CHB, bytes, mb);
        }
    }

    colp[w*160 + l]       = c0;
    colp[w*160 + l + 32]  = c1;
    colp[w*160 + l + 64]  = c2;
    colp[w*160 + l + 96]  = c3;
    if (q4ok) colp[w*160 + l + 128] = c4;
    __syncthreads();

    /* ---- epilogue: fold partials, qa, fused double-BCE (fast-math) ---- */
    float s = 0.f;
    if (t < C) {
        float col = 0.f;
        #pragma unroll
        for (int ww = 0; ww < NW; ww++) col += colp[ww*160 + t];
        float r0 = 0.f, r1 = 0.f, r2 = 0.f, r3 = 0.f;
        const float* rp = rowpart + t*RPAD;
        #pragma unroll
        for (int j = 0; j < 32; j += 4) {
            r0 += rp[j]; r1 += rp[j+1]; r2 += rp[j+2]; r3 += rp[j+3];
        }
        float x = av + col + ((r0 + r1) + (r2 + r3));
        float qa = 1.f / (1.f + __expf(-x));
        out[n*C + t] = qa;
        float p1 = fminf(fmaxf(qa, EPSV), 1.f - EPSV);
        s  = tg*__logf(p1) + (1.f - tg)*__logf(1.f - p1);
        float p2 = 1.f / (1.f + __expf(-av));
        p2 = fminf(fmaxf(p2, EPSV), 1.f - EPSV);
        s += tg*__logf(p2) + (1.f - tg)*__logf(1.f - p2);
    }
    #pragma unroll
    for (int off = 16; off > 0; off >>= 1)
        s += __shfl_xor_sync(0xFFFFFFFFu, s, off);
    if (l == 0) wsum[w] = s;
    __syncthreads();
    if (t == 0) {
        float bs = 0.f;
        #pragma unroll
        for (int ww = 0; ww < NW; ww++) bs += wsum[ww];
        g_partial[n] = bs;
        __threadfence();
        unsigned old = atomicAdd(&g_count, 1u);
        sm[S_LAST] = (old == N - 1) ? 1.f : 0.f;
    }
    __syncthreads();

    /* ---- last CTA folds the 512 partials (deterministic fixed order) ---- */
    if (sm[S_LAST] != 0.f) {
        float ps = 0.f;
        if (t < 128)
            ps = (g_partial[t] + g_partial[t + 128])
               + (g_partial[t + 256] + g_partial[t + 384]);
        #pragma unroll
        for (int off = 16; off > 0; off >>= 1)
            ps += __shfl_xor_sync(0xFFFFFFFFu, ps, off);
        if (l == 0) wsum[w] = ps;
        __syncthreads();
        if (t == 0) {
            float tot = ((wsum[0] + wsum[1]) + (wsum[2] + wsum[3]));
            if (out_size > NC) out[NC] = -tot / (3.0f * (float)NC);
            g_count = 0;        /* reset for next graph replay */
        }
    }
}

extern "C" void kernel_launch(void* const* d_in, const int* in_sizes, int n_in,
                              void* d_out, int out_size) {
    const float* a           = (const float*)d_in[0];
    const float* aa          = (const float*)d_in[1];
    const float* target      = (const float*)d_in[2];
    const float* bank_values = (const float*)d_in[3];
    const int*   bank_times  = (const int*)d_in[4];
    const int*   bank_mask   = (const int*)d_in[5];
    const int*   ids         = (const int*)d_in[6];
    const int*   times       = (const int*)d_in[7];
    float* out = (float*)d_out;

    cudaFuncSetAttribute(fused_kernel,
                         cudaFuncAttributeMaxDynamicSharedMemorySize, SMEM_BYTES);
    fused_kernel<<<N, NT, SMEM_BYTES>>>(a, aa, target, bank_values, bank_times,
                                        bank_mask, ids, times, out, out_size);
}

// round 14
// speedup vs baseline: 1.4289x; 1.4289x over previous
#include <cuda_runtime.h>
#include <math.h>

#define N 512
#define C 157
#define M 20
#define NC (N*C)
#define SIGMA2_INV (1.0f/(2.0f*300.0f*300.0f))
#define EPSV 1e-7f
#define INV_DECAY (1.0f/0.9f)
#define LOG2_INV_DECAY 0.15200309344504997f   /* log2(1/0.9) */
#define RPAD 33                                /* rowpart pitch (conflict-free) */
#define NW 6                                   /* warps per CTA */
#define NT (NW*32)                             /* 192 threads */
#define RH 79                                  /* rows in half 0 (half1: 78) */

__device__ float pre_g[N * C];                 /* zero-init; re-zeroed each replay */
__device__ unsigned int cnt_g[N];              /* per-n arrival counter */
__device__ float g_partial[N];
__device__ unsigned int g_count = 0;

__global__ __launch_bounds__(NT, 8) void fused_kernel(
    const float* __restrict__ a, const float* __restrict__ aa,
    const float* __restrict__ target, const float* __restrict__ bank_values,
    const int* __restrict__ bank_times, const int* __restrict__ bank_mask,
    const int* __restrict__ ids, const int* __restrict__ times,
    float* __restrict__ out, int out_size)
{
    __shared__ float msg_s[C], fmsg_s[C];
    __shared__ float rowpart[RH * RPAD];    /* [local row][lane] */
    __shared__ float colpart[NW][160];      /* per-warp col partials */
    __shared__ float wpast[M], wfut[M];
    __shared__ float denp_s, denf_s;
    __shared__ float wsum[NW];
    __shared__ int flag_s;

    const int bid = blockIdx.x;
    const int n = bid >> 1;
    const int half = bid & 1;
    const int base = half * RH;
    const int rows_h = half ? (C - RH) : RH;   /* 78 : 79 */
    const int t = threadIdx.x;
    const int w = t >> 5;
    const int l = t & 31;
    const int id = ids[n];
    const float* aa_g = aa + (size_t)n * (C*C);

    /* ---- prefetch bank row into registers (before any barrier) ---- */
    float v[M];
    if (t < C) {
        const float* vals = bank_values + (size_t)id * (M*C);
        #pragma unroll
        for (int m = 0; m < M; m++) v[m] = vals[m*C + t];
    }

    /* ---- temporal weights: warp 0, ballot-rank ---- */
    if (t < 32) {
        const bool vd = l < M;
        int tsi = 0, mk = 0;
        if (vd) { tsi = bank_times[id*M + l]; mk = bank_mask[id*M + l]; }
        const float t0 = (float)times[n];
        float ts = (float)tsi;
        float d = ts - t0;
        float kern = __expf(-d*d*SIGMA2_INV);
        bool condp = vd && mk && (ts < t0);
        bool condf = vd && mk && (ts > t0);
        unsigned bp = __ballot_sync(0xFFFFFFFFu, condp);
        unsigned bf = __ballot_sync(0xFFFFFFFFu, condf);
        unsigned below = (1u << l) - 1u;
        float dwp = condp ? exp2f(LOG2_INV_DECAY * (float)__popc(bp & below)) : 0.f;
        float dwf = condf ? exp2f(LOG2_INV_DECAY * (float)__popc(bf & below)) : 0.f;
        if (vd) { wpast[l] = dwp * kern; wfut[l] = dwf * kern; }
        if (l == 0) {
            float cp_ = (float)__popc(bp), cf_ = (float)__popc(bf);
            denp_s = (exp2f(LOG2_INV_DECAY * cp_) - 1.f) / (INV_DECAY - 1.f);
            denf_s = (exp2f(LOG2_INV_DECAY * cf_) - 1.f) / (INV_DECAY - 1.f);
        }
    }
    __syncthreads();

    /* ---- msg/fmsg from registers ---- */
    if (t < C) {
        float nump = 0.f, numf = 0.f;
        #pragma unroll
        for (int m = 0; m < M; m++) {
            nump = fmaf(wpast[m], v[m], nump);
            numf = fmaf(wfut[m],  v[m], numf);
        }
        float denp = denp_s, denf = denf_s;
        msg_s[t]  = (denp > 0.f) ? nump / fmaxf(denp, EPSV) : 0.f;
        fmsg_s[t] = (denf > 0.f) ? numf / fmaxf(denf, EPSV) : 0.f;
    }
    __syncthreads();

    /* ---- stream this CTA's row-half of aa (proven scalar-LDG scheme) ---- */
    const bool q4ok = (l + 128) < C;
    float fm0 = fmsg_s[l];
    float fm1 = fmsg_s[l + 32];
    float fm2 = fmsg_s[l + 64];
    float fm3 = fmsg_s[l + 96];
    float fm4 = q4ok ? fmsg_s[l + 128] : 0.f;
    float c0 = 0.f, c1 = 0.f, c2 = 0.f, c3 = 0.f, c4 = 0.f;

    #pragma unroll 2
    for (int k = 0; k < 14; k++) {
        int ri = w + NW*k;
        if (ri < rows_h) {
            const float* rp = aa_g + (base + ri)*C;
            float v0 = rp[l];
            float v1 = rp[l + 32];
            float v2 = rp[l + 64];
            float v3 = rp[l + 96];
            float v4 = q4ok ? rp[l + 128] : 0.f;
            float mi = msg_s[base + ri];          /* broadcast LDS */
            c0 = fmaf(v0, mi, c0);
            c1 = fmaf(v1, mi, c1);
            c2 = fmaf(v2, mi, c2);
            c3 = fmaf(v3, mi, c3);
            c4 = fmaf(v4, mi, c4);
            float rs = fmaf(v0, fm0, v1*fm1) + fmaf(v2, fm2, v3*fm3) + v4*fm4;
            rowpart[ri*RPAD + l] = rs;
        }
    }
    colpart[w][l]       = c0;
    colpart[w][l + 32]  = c1;
    colpart[w][l + 64]  = c2;
    colpart[w][l + 96]  = c3;
    if (q4ok) colpart[w][l + 128] = c4;
    __syncthreads();

    /* ---- fold partials; one deterministic RED per j into pre_g[n][j] ---- */
    if (t < C) {
        float colsum = 0.f;
        #pragma unroll
        for (int ww = 0; ww < NW; ww++) colsum += colpart[ww][t];
        float rowv = 0.f;
        int ri = t - base;
        if (ri >= 0 && ri < rows_h) {
            float r0 = 0.f, r1 = 0.f, r2 = 0.f, r3 = 0.f;
            const float* rp = rowpart + ri*RPAD;
            #pragma unroll
            for (int j = 0; j < 32; j += 4) {
                r0 += rp[j]; r1 += rp[j+1]; r2 += rp[j+2]; r3 += rp[j+3];
            }
            rowv = (r0 + r1) + (r2 + r3);
        }
        atomicAdd(&pre_g[n*C + t], colsum + rowv);   /* RED: exactly 2 adds/cell */
    }
    __threadfence();                                  /* each thread fences its RED */
    __syncthreads();
    if (t == 0) flag_s = (int)atomicAdd(&cnt_g[n], 1u);
    __syncthreads();

    if (flag_s == 1) {
        /* ---- second finisher: qa + double-BCE for this n ---- */
        __threadfence();                              /* acquire peer's REDs */
        float s = 0.f;
        if (t < C) {
            float p  = __ldcg(&pre_g[n*C + t]);       /* L2 read (RED bypassed L1) */
            float av = a[n*C + t];
            float tg = target[n*C + t];
            float x = av + p;
            float qa = 1.f / (1.f + __expf(-x));
            out[n*C + t] = qa;
            float p1 = fminf(fmaxf(qa, EPSV), 1.f - EPSV);
            s  = tg*__logf(p1) + (1.f - tg)*__logf(1.f - p1);
            float p2 = 1.f / (1.f + __expf(-av));
            p2 = fminf(fmaxf(p2, EPSV), 1.f - EPSV);
            s += tg*__logf(p2) + (1.f - tg)*__logf(1.f - p2);
            pre_g[n*C + t] = 0.f;                     /* re-zero for next replay */
        }
        #pragma unroll
        for (int off = 16; off > 0; off >>= 1)
            s += __shfl_xor_sync(0xFFFFFFFFu, s, off);
        if (l == 0) wsum[w] = s;
        __syncthreads();
        if (t == 0) {
            cnt_g[n] = 0;                             /* reset for next replay */
            float bs = ((wsum[0] + wsum[1]) + (wsum[2] + wsum[3]))
                     + (wsum[4] + wsum[5]);
            g_partial[n] = bs;
            __threadfence();
            unsigned old = atomicAdd(&g_count, 1u);
            flag_s = (old == N - 1) ? 2 : 0;
        }
        __syncthreads();

        /* ---- last finisher folds the 512 partials (deterministic order) ---- */
        if (flag_s == 2) {
            float ps = 0.f;
            if (t < 128)
                ps = (g_partial[t] + g_partial[t + 128])
                   + (g_partial[t + 256] + g_partial[t + 384]);
            #pragma unroll
            for (int off = 16; off > 0; off >>= 1)
                ps += __shfl_xor_sync(0xFFFFFFFFu, ps, off);
            if (l == 0) wsum[w] = ps;
            __syncthreads();
            if (t == 0) {
                float tot = ((wsum[0] + wsum[1]) + (wsum[2] + wsum[3]));
                if (out_size > NC) out[NC] = -tot / (3.0f * (float)NC);
                g_count = 0;                          /* reset for next replay */
            }
        }
    }
}

extern "C" void kernel_launch(void* const* d_in, const int* in_sizes, int n_in,
                              void* d_out, int out_size) {
    const float* a           = (const float*)d_in[0];
    const float* aa          = (const float*)d_in[1];
    const float* target      = (const float*)d_in[2];
    const float* bank_values = (const float*)d_in[3];
    const int*   bank_times  = (const int*)d_in[4];
    const int*   bank_mask   = (const int*)d_in[5];
    const int*   ids         = (const int*)d_in[6];
    const int*   times       = (const int*)d_in[7];
    float* out = (float*)d_out;

    fused_kernel<<<2*N, NT>>>(a, aa, target, bank_values, bank_times,
                              bank_mask, ids, times, out, out_size);
}